// round 5
// baseline (speedup 1.0000x reference)
#include <cuda_runtime.h>

#define NF 16        // filters
#define FF 2000      // features
#define DC 512       // coordinate (reduction) dim
#define NB 64        // batch
#define KNN 8        // neighbors
#define IPAD 2048    // padded feature dim for the packed operand

// Scratch (static device globals — no allocation at runtime)
__device__ float g_Xp[(size_t)NF * DC * IPAD];        // 64 MB packed [f][c][i]
__device__ float g_sq[NF * FF];                       // column squared norms
__device__ float g_dist[(size_t)NF * FF * FF];        // 256 MB distances [f][i][j]
__device__ int   g_idx[FF * KNN * NF];                // neighbor indices [(i*8+k)*16 + f]

// ---------------------------------------------------------------------------
// sq[f][i] = sum_c coord[c][i][f]^2, emulating XLA's GPU column-reduction
// order bit-exactly (DO NOT TOUCH — verified rel_err == 0.0):
//   partial[y] = sum_{m=0..15, ascending} fadd(p, fmul(x[y+32m], x[y+32m]))
//   result = shfl_down butterfly tree over y with offsets 16,8,4,2,1
// ---------------------------------------------------------------------------
__global__ __launch_bounds__(1024) void sq_kernel(const float* __restrict__ coord) {
    __shared__ float s[32][33];
    const int tx = threadIdx.x & 31;   // output lane (minor dim of (i,f) flat)
    const int ty = threadIdx.x >> 5;   // reduce lane
    const int outbase = blockIdx.x * 32;
    const int out = outbase + tx;      // flat index i*16 + f, 0..31999

    float acc = 0.0f;
    #pragma unroll
    for (int m = 0; m < 16; m++) {
        int c = ty + 32 * m;
        float v = coord[(size_t)c * (FF * NF) + out];
        acc = __fadd_rn(acc, __fmul_rn(v, v));
    }
    s[ty][tx] = acc;
    __syncthreads();

    float v = s[tx][ty];               // lane tx holds partial[tx] of output ty
    #pragma unroll
    for (int off = 16; off; off >>= 1)
        v = __fadd_rn(v, __shfl_down_sync(0xffffffffu, v, off));

    if (tx == 0) {
        int o = outbase + ty;          // flat i*16 + f
        int f = o & 15;
        int i = o >> 4;
        g_sq[f * FF + i] = v;
    }
}

// ---------------------------------------------------------------------------
// Pack coords (c, i, f) -> Xp[f][c][i], zero-padding i in [2000, 2048).
// ---------------------------------------------------------------------------
__global__ void pack_kernel(const float* __restrict__ coord) {
    __shared__ float s[64][17];  // padded to kill bank conflicts
    const int c = blockIdx.y;
    const int ibase = blockIdx.x * 64;
    const int t = threadIdx.x;

    int il = t >> 2;             // 0..63 local i
    int f0 = (t & 3) * 4;        // 0,4,8,12
    float4 v = make_float4(0.f, 0.f, 0.f, 0.f);
    if (ibase + il < FF) {
        v = *(const float4*)(coord + (size_t)c * FF * NF + (size_t)(ibase + il) * NF + f0);
    }
    s[il][f0 + 0] = v.x;
    s[il][f0 + 1] = v.y;
    s[il][f0 + 2] = v.z;
    s[il][f0 + 3] = v.w;
    __syncthreads();

    int i2 = t & 63;
    int fhi = t >> 6;  // 0..3
    #pragma unroll
    for (int pph = 0; pph < 4; pph++) {
        int f = pph * 4 + fhi;
        g_Xp[((size_t)f * DC + c) * IPAD + ibase + i2] = s[i2][f];
    }
}

// ---------------------------------------------------------------------------
// Per-filter syrk + distance epilogue (R3 scalar version — REVERTED from the
// f32x2 experiment, which ptxas emulated at ~3x cost).
// 128x128 tile / block, 256 threads, 8x8 per thread, k-step 8.
// Upper-triangular tiles only; off-diagonal tiles write the mirror too.
// Single strictly k-ascending FMA chain per output (bit-exact vs reference).
// ---------------------------------------------------------------------------
__global__ __launch_bounds__(256, 2) void gram_kernel() {
    const int f = blockIdx.z;

    // Decode linear upper-triangular tile index -> (ti, tj), ti <= tj
    int p = blockIdx.x;
    int ti = 0;
    while (p >= (16 - ti)) { p -= (16 - ti); ti++; }
    const int tj = ti + p;

    const float* X = g_Xp + (size_t)f * DC * IPAD;
    __shared__ float As[8][128];
    __shared__ float Bs[8][128];

    const int t  = threadIdx.x;
    const int kl = t >> 5;            // 0..7 smem row to fill
    const int i4 = (t & 31) << 2;     // float4 column offset
    const int tx = t & 15;
    const int ty = t >> 4;
    const int Ib = ti << 7;
    const int Jb = tj << 7;

    float acc[8][8];
    #pragma unroll
    for (int u = 0; u < 8; u++)
        #pragma unroll
        for (int v = 0; v < 8; v++) acc[u][v] = 0.0f;

    float4 ra = *(const float4*)(X + (size_t)kl * IPAD + Ib + i4);
    float4 rb = *(const float4*)(X + (size_t)kl * IPAD + Jb + i4);

    for (int k0 = 0; k0 < DC; k0 += 8) {
        *(float4*)&As[kl][i4] = ra;
        *(float4*)&Bs[kl][i4] = rb;
        __syncthreads();
        if (k0 + 8 < DC) {
            ra = *(const float4*)(X + (size_t)(k0 + 8 + kl) * IPAD + Ib + i4);
            rb = *(const float4*)(X + (size_t)(k0 + 8 + kl) * IPAD + Jb + i4);
        }
        #pragma unroll
        for (int kk = 0; kk < 8; kk++) {
            float a[8], b[8];
            *(float4*)&a[0] = *(const float4*)&As[kk][ty * 8];
            *(float4*)&a[4] = *(const float4*)&As[kk][ty * 8 + 4];
            *(float4*)&b[0] = *(const float4*)&Bs[kk][tx * 8];
            *(float4*)&b[4] = *(const float4*)&Bs[kk][tx * 8 + 4];
            #pragma unroll
            for (int u = 0; u < 8; u++)
                #pragma unroll
                for (int v = 0; v < 8; v++)
                    acc[u][v] = fmaf(a[u], b[v], acc[u][v]);
        }
        __syncthreads();
    }

    // Epilogue: dist = max(sq_i + sq_j - 2*G, 0). 2*acc is exact (power of 2),
    // identical rounding to the reference regardless of contraction.
    const int gib = Ib + ty * 8;
    const int gjb = Jb + tx * 8;
    #pragma unroll
    for (int u = 0; u < 8; u++) {
        int gi = gib + u;
        if (gi >= FF) continue;
        float si = g_sq[f * FF + gi];
        #pragma unroll
        for (int v = 0; v < 8; v++) {
            int gj = gjb + v;
            if (gj >= FF) continue;
            float sj = g_sq[f * FF + gj];
            float d = fmaxf(si + sj - 2.0f * acc[u][v], 0.0f);
            g_dist[((size_t)f * FF + gi) * FF + gj] = d;
            if (ti != tj)
                g_dist[((size_t)f * FF + gj) * FF + gi] = d;
        }
    }
}

// ---------------------------------------------------------------------------
// Top-8 smallest per row (warp per row). float4 streaming loads + float-only
// fast-reject guard; u64 (dist_bits<<32 | j) keys preserve exact lax.top_k
// tie-break (lower j first). Sentinel = FLT_MAX so the guard never sees NaN.
// launch_bounds(256,4) to lift occupancy (was reg-limited to 2 CTAs/SM).
// ---------------------------------------------------------------------------
#define SENT_KEY 0x7F7FFFFFFFFFFFFFULL   // (FLT_MAX bits << 32) | 0xFFFFFFFF

__global__ __launch_bounds__(256, 4) void topk_kernel() {
    const int warp = (blockIdx.x * blockDim.x + threadIdx.x) >> 5;
    const int lane = threadIdx.x & 31;
    if (warp >= NF * FF) return;

    const float4* __restrict__ row4 = (const float4*)(g_dist + (size_t)warp * FF);

    unsigned long long k[8];
    #pragma unroll
    for (int s = 0; s < 8; s++) k[s] = SENT_KEY;
    float k7f = 3.402823466e+38f;  // FLT_MAX

    // Per-lane j's ascend, so for d strictly < k7f a u64-insert is always a
    // displacement; d == k7f can never displace (same-lane index is larger).
#define TOPK_TRY(dv, jv)                                                     \
    if ((dv) < k7f) {                                                        \
        unsigned long long key =                                             \
            ((unsigned long long)__float_as_uint(dv) << 32) | (unsigned)(jv);\
        k[7] = key;                                                          \
        _Pragma("unroll")                                                    \
        for (int s = 7; s > 0; s--) {                                        \
            if (k[s] < k[s - 1]) {                                           \
                unsigned long long tmp = k[s]; k[s] = k[s - 1]; k[s - 1] = tmp;\
            }                                                                \
        }                                                                    \
        k7f = __uint_as_float((unsigned)(k[7] >> 32));                       \
    }

    #pragma unroll 2
    for (int m = lane; m < FF / 4; m += 32) {
        float4 v = row4[m];
        int j0 = m << 2;
        TOPK_TRY(v.x, j0 + 0);
        TOPK_TRY(v.y, j0 + 1);
        TOPK_TRY(v.z, j0 + 2);
        TOPK_TRY(v.w, j0 + 3);
    }
#undef TOPK_TRY

    const int f = warp / FF;
    const int i = warp % FF;

    int head = 0;
    for (int r = 0; r < KNN; r++) {
        unsigned long long v = (head < 8) ? k[head] : 0xFFFFFFFFFFFFFFFFULL;
        unsigned long long m = v;
        #pragma unroll
        for (int off = 16; off; off >>= 1) {
            unsigned long long o = __shfl_xor_sync(0xffffffffu, m, off);
            m = (o < m) ? o : m;
        }
        if (v == m) head++;  // keys unique (index embedded) -> single winner
        if (lane == 0)
            g_idx[(i * KNN + r) * NF + f] = (int)(m & 0xFFFFFFFFu);
    }
}

// ---------------------------------------------------------------------------
// out[b][i*8+k][c] = inputs[b][ idx[i][k][c] ][c]
// ---------------------------------------------------------------------------
__global__ void gather_kernel(const float* __restrict__ inputs,
                              float* __restrict__ out) {
    int g = blockIdx.x * blockDim.x + threadIdx.x;
    const int total = NB * FF * KNN * NF;
    if (g >= total) return;
    int c   = g & 15;
    int row = (g >> 4) % (FF * KNN);
    int b   = g / (FF * KNN * NF);
    int r   = g_idx[row * NF + c];
    out[g] = inputs[((size_t)b * FF + r) * NF + c];
}

// ---------------------------------------------------------------------------
extern "C" void kernel_launch(void* const* d_in, const int* in_sizes, int n_in,
                              void* d_out, int out_size) {
    const float* inputs = (const float*)d_in[0];   // (64, 2000, 16)
    const float* coords = (const float*)d_in[1];   // (512, 2000, 16)
    if (n_in >= 2 && in_sizes[0] == DC * FF * NF) {
        coords = (const float*)d_in[0];
        inputs = (const float*)d_in[1];
    }

    sq_kernel<<<FF * NF / 32, 1024>>>(coords);
    pack_kernel<<<dim3(32, DC), 256>>>(coords);
    gram_kernel<<<dim3(136, 1, NF), 256>>>();
    topk_kernel<<<(NF * FF) / 8, 256>>>();
    gather_kernel<<<(NB * FF * KNN * NF) / 256, 256>>>(inputs, (float*)d_out);
}

// round 6
// speedup vs baseline: 2.2415x; 2.2415x over previous
#include <cuda_runtime.h>

#define NF 16        // filters
#define FF 2000      // features
#define DC 512       // coordinate (reduction) dim
#define NB 64        // batch
#define KNN 8        // neighbors
#define IPAD 2048    // padded feature dim for the packed operand

// Scratch (static device globals — no allocation at runtime)
__device__ float g_Xp[(size_t)NF * DC * IPAD];        // 64 MB packed [f][c][i]
__device__ float g_sq[NF * FF];                       // column squared norms
__device__ float g_dist[(size_t)NF * FF * FF];        // 256 MB distances [f][i][j]
__device__ int   g_idx[FF * KNN * NF];                // neighbor indices [(i*8+k)*16 + f]

// ---------------------------------------------------------------------------
// sq[f][i] = sum_c coord[c][i][f]^2, emulating XLA's GPU column-reduction
// order bit-exactly (DO NOT TOUCH — verified rel_err == 0.0):
//   partial[y] = sum_{m=0..15, ascending} fadd(p, fmul(x[y+32m], x[y+32m]))
//   result = shfl_down butterfly tree over y with offsets 16,8,4,2,1
// ---------------------------------------------------------------------------
__global__ __launch_bounds__(1024) void sq_kernel(const float* __restrict__ coord) {
    __shared__ float s[32][33];
    const int tx = threadIdx.x & 31;   // output lane (minor dim of (i,f) flat)
    const int ty = threadIdx.x >> 5;   // reduce lane
    const int outbase = blockIdx.x * 32;
    const int out = outbase + tx;      // flat index i*16 + f, 0..31999

    float acc = 0.0f;
    #pragma unroll
    for (int m = 0; m < 16; m++) {
        int c = ty + 32 * m;
        float v = coord[(size_t)c * (FF * NF) + out];
        acc = __fadd_rn(acc, __fmul_rn(v, v));
    }
    s[ty][tx] = acc;
    __syncthreads();

    float v = s[tx][ty];               // lane tx holds partial[tx] of output ty
    #pragma unroll
    for (int off = 16; off; off >>= 1)
        v = __fadd_rn(v, __shfl_down_sync(0xffffffffu, v, off));

    if (tx == 0) {
        int o = outbase + ty;          // flat i*16 + f
        int f = o & 15;
        int i = o >> 4;
        g_sq[f * FF + i] = v;
    }
}

// ---------------------------------------------------------------------------
// Pack coords (c, i, f) -> Xp[f][c][i], zero-padding i in [2000, 2048).
// ---------------------------------------------------------------------------
__global__ void pack_kernel(const float* __restrict__ coord) {
    __shared__ float s[64][17];  // padded to kill bank conflicts
    const int c = blockIdx.y;
    const int ibase = blockIdx.x * 64;
    const int t = threadIdx.x;

    int il = t >> 2;             // 0..63 local i
    int f0 = (t & 3) * 4;        // 0,4,8,12
    float4 v = make_float4(0.f, 0.f, 0.f, 0.f);
    if (ibase + il < FF) {
        v = *(const float4*)(coord + (size_t)c * FF * NF + (size_t)(ibase + il) * NF + f0);
    }
    s[il][f0 + 0] = v.x;
    s[il][f0 + 1] = v.y;
    s[il][f0 + 2] = v.z;
    s[il][f0 + 3] = v.w;
    __syncthreads();

    int i2 = t & 63;
    int fhi = t >> 6;  // 0..3
    #pragma unroll
    for (int pph = 0; pph < 4; pph++) {
        int f = pph * 4 + fhi;
        g_Xp[((size_t)f * DC + c) * IPAD + ibase + i2] = s[i2][f];
    }
}

// ---------------------------------------------------------------------------
// Per-filter syrk + distance epilogue (R3 scalar version, at ~96% of the
// FFMA issue roofline — DO NOT TOUCH).
// 128x128 tile / block, 256 threads, 8x8 per thread, k-step 8.
// Single strictly k-ascending FMA chain per output (bit-exact vs reference).
// ---------------------------------------------------------------------------
__global__ __launch_bounds__(256, 2) void gram_kernel() {
    const int f = blockIdx.z;

    // Decode linear upper-triangular tile index -> (ti, tj), ti <= tj
    int p = blockIdx.x;
    int ti = 0;
    while (p >= (16 - ti)) { p -= (16 - ti); ti++; }
    const int tj = ti + p;

    const float* X = g_Xp + (size_t)f * DC * IPAD;
    __shared__ float As[8][128];
    __shared__ float Bs[8][128];

    const int t  = threadIdx.x;
    const int kl = t >> 5;            // 0..7 smem row to fill
    const int i4 = (t & 31) << 2;     // float4 column offset
    const int tx = t & 15;
    const int ty = t >> 4;
    const int Ib = ti << 7;
    const int Jb = tj << 7;

    float acc[8][8];
    #pragma unroll
    for (int u = 0; u < 8; u++)
        #pragma unroll
        for (int v = 0; v < 8; v++) acc[u][v] = 0.0f;

    float4 ra = *(const float4*)(X + (size_t)kl * IPAD + Ib + i4);
    float4 rb = *(const float4*)(X + (size_t)kl * IPAD + Jb + i4);

    for (int k0 = 0; k0 < DC; k0 += 8) {
        *(float4*)&As[kl][i4] = ra;
        *(float4*)&Bs[kl][i4] = rb;
        __syncthreads();
        if (k0 + 8 < DC) {
            ra = *(const float4*)(X + (size_t)(k0 + 8 + kl) * IPAD + Ib + i4);
            rb = *(const float4*)(X + (size_t)(k0 + 8 + kl) * IPAD + Jb + i4);
        }
        #pragma unroll
        for (int kk = 0; kk < 8; kk++) {
            float a[8], b[8];
            *(float4*)&a[0] = *(const float4*)&As[kk][ty * 8];
            *(float4*)&a[4] = *(const float4*)&As[kk][ty * 8 + 4];
            *(float4*)&b[0] = *(const float4*)&Bs[kk][tx * 8];
            *(float4*)&b[4] = *(const float4*)&Bs[kk][tx * 8 + 4];
            #pragma unroll
            for (int u = 0; u < 8; u++)
                #pragma unroll
                for (int v = 0; v < 8; v++)
                    acc[u][v] = fmaf(a[u], b[v], acc[u][v]);
        }
        __syncthreads();
    }

    // Epilogue: dist = max(sq_i + sq_j - 2*G, 0). 2*acc is exact (power of 2),
    // identical rounding to the reference regardless of contraction.
    const int gib = Ib + ty * 8;
    const int gjb = Jb + tx * 8;
    #pragma unroll
    for (int u = 0; u < 8; u++) {
        int gi = gib + u;
        if (gi >= FF) continue;
        float si = g_sq[f * FF + gi];
        #pragma unroll
        for (int v = 0; v < 8; v++) {
            int gj = gjb + v;
            if (gj >= FF) continue;
            float sj = g_sq[f * FF + gj];
            float d = fmaxf(si + sj - 2.0f * acc[u][v], 0.0f);
            g_dist[((size_t)f * FF + gi) * FF + gj] = d;
            if (ti != tj)
                g_dist[((size_t)f * FF + gj) * FF + gi] = d;
        }
    }
}

// ---------------------------------------------------------------------------
// Top-8 smallest per row (warp per row). R3 semantics (u64 packed keys,
// identical insert + merge + tie-break), but loads are BATCHED: 8 independent
// LDGs fill registers before any data-dependent compare, lifting MLP from
// ~0.65 (R3, 376us) to ~8. No launch_bounds cap — R4's (256,4) spilled k[8]
// to local memory and caused a 8x regression.
// Row coverage: 8 batches x (8 taps x stride 32) = 2048 >= 2000; batch 7 is
// bounds-checked.
// ---------------------------------------------------------------------------
__global__ void topk_kernel() {
    const int warp = (blockIdx.x * blockDim.x + threadIdx.x) >> 5;
    const int lane = threadIdx.x & 31;
    if (warp >= NF * FF) return;

    const float* __restrict__ row = g_dist + (size_t)warp * FF;

    unsigned long long k[8];
    #pragma unroll
    for (int s = 0; s < 8; s++) k[s] = 0xFFFFFFFFFFFFFFFFULL;

    for (int b = 0; b < 8; b++) {
        const int base = b * 256 + lane;
        // Phase A: 8 independent loads (no consumer in between) -> MLP = 8
        float d[8];
        #pragma unroll
        for (int t = 0; t < 8; t++) {
            int j = base + t * 32;
            d[t] = (j < FF) ? row[j] : 0.0f;   // pad value unused (guarded below)
        }
        // Phase B: process (exact R3 insert logic)
        #pragma unroll
        for (int t = 0; t < 8; t++) {
            int j = base + t * 32;
            unsigned long long key =
                ((unsigned long long)__float_as_uint(d[t]) << 32) | (unsigned)j;
            if (j < FF && key < k[7]) {
                k[7] = key;
                #pragma unroll
                for (int s = 7; s > 0; s--) {
                    if (k[s] < k[s - 1]) {
                        unsigned long long tmp = k[s];
                        k[s] = k[s - 1];
                        k[s - 1] = tmp;
                    }
                }
            }
        }
    }

    const int f = warp / FF;
    const int i = warp % FF;

    int head = 0;
    for (int r = 0; r < KNN; r++) {
        unsigned long long v = (head < 8) ? k[head] : 0xFFFFFFFFFFFFFFFFULL;
        unsigned long long m = v;
        #pragma unroll
        for (int off = 16; off; off >>= 1) {
            unsigned long long o = __shfl_xor_sync(0xffffffffu, m, off);
            m = (o < m) ? o : m;
        }
        if (v == m) head++;  // keys unique (index embedded) -> single winner
        if (lane == 0)
            g_idx[(i * KNN + r) * NF + f] = (int)(m & 0xFFFFFFFFu);
    }
}

// ---------------------------------------------------------------------------
// out[b][i*8+k][c] = inputs[b][ idx[i][k][c] ][c]
// ---------------------------------------------------------------------------
__global__ void gather_kernel(const float* __restrict__ inputs,
                              float* __restrict__ out) {
    int g = blockIdx.x * blockDim.x + threadIdx.x;
    const int total = NB * FF * KNN * NF;
    if (g >= total) return;
    int c   = g & 15;
    int row = (g >> 4) % (FF * KNN);
    int b   = g / (FF * KNN * NF);
    int r   = g_idx[row * NF + c];
    out[g] = inputs[((size_t)b * FF + r) * NF + c];
}

// ---------------------------------------------------------------------------
extern "C" void kernel_launch(void* const* d_in, const int* in_sizes, int n_in,
                              void* d_out, int out_size) {
    const float* inputs = (const float*)d_in[0];   // (64, 2000, 16)
    const float* coords = (const float*)d_in[1];   // (512, 2000, 16)
    if (n_in >= 2 && in_sizes[0] == DC * FF * NF) {
        coords = (const float*)d_in[0];
        inputs = (const float*)d_in[1];
    }

    sq_kernel<<<FF * NF / 32, 1024>>>(coords);
    pack_kernel<<<dim3(32, DC), 256>>>(coords);
    gram_kernel<<<dim3(136, 1, NF), 256>>>();
    topk_kernel<<<(NF * FF) / 8, 256>>>();
    gather_kernel<<<(NB * FF * KNN * NF) / 256, 256>>>(inputs, (float*)d_out);
}

// round 8
// speedup vs baseline: 2.2947x; 1.0237x over previous
#include <cuda_runtime.h>

#define NF 16        // filters
#define FF 2000      // features
#define DC 512       // coordinate (reduction) dim
#define NB 64        // batch
#define KNN 8        // neighbors
#define IPAD 2048    // padded feature dim for the packed operand

// Scratch (static device globals — no allocation at runtime)
__device__ float g_Xp[(size_t)NF * DC * IPAD];        // 64 MB packed [f][c][i]
__device__ float g_sq[NF * FF];                       // column squared norms
__device__ float g_dist[(size_t)NF * FF * FF];        // 256 MB distances [f][i][j]
__device__ int   g_idx[FF * KNN * NF];                // neighbor indices [(i*8+k)*16 + f]

// ---------------------------------------------------------------------------
// sq[f][i] = sum_c coord[c][i][f]^2, emulating XLA's GPU column-reduction
// order bit-exactly (DO NOT TOUCH — verified rel_err == 0.0):
//   partial[y] = sum_{m=0..15, ascending} fadd(p, fmul(x[y+32m], x[y+32m]))
//   result = shfl_down butterfly tree over y with offsets 16,8,4,2,1
// ---------------------------------------------------------------------------
__global__ __launch_bounds__(1024) void sq_kernel(const float* __restrict__ coord) {
    __shared__ float s[32][33];
    const int tx = threadIdx.x & 31;   // output lane (minor dim of (i,f) flat)
    const int ty = threadIdx.x >> 5;   // reduce lane
    const int outbase = blockIdx.x * 32;
    const int out = outbase + tx;      // flat index i*16 + f, 0..31999

    float acc = 0.0f;
    #pragma unroll
    for (int m = 0; m < 16; m++) {
        int c = ty + 32 * m;
        float v = coord[(size_t)c * (FF * NF) + out];
        acc = __fadd_rn(acc, __fmul_rn(v, v));
    }
    s[ty][tx] = acc;
    __syncthreads();

    float v = s[tx][ty];               // lane tx holds partial[tx] of output ty
    #pragma unroll
    for (int off = 16; off; off >>= 1)
        v = __fadd_rn(v, __shfl_down_sync(0xffffffffu, v, off));

    if (tx == 0) {
        int o = outbase + ty;          // flat i*16 + f
        int f = o & 15;
        int i = o >> 4;
        g_sq[f * FF + i] = v;
    }
}

// ---------------------------------------------------------------------------
// Pack coords (c, i, f) -> Xp[f][c][i], zero-padding i in [2000, 2048).
// ---------------------------------------------------------------------------
__global__ void pack_kernel(const float* __restrict__ coord) {
    __shared__ float s[64][17];  // padded to kill bank conflicts
    const int c = blockIdx.y;
    const int ibase = blockIdx.x * 64;
    const int t = threadIdx.x;

    int il = t >> 2;             // 0..63 local i
    int f0 = (t & 3) * 4;        // 0,4,8,12
    float4 v = make_float4(0.f, 0.f, 0.f, 0.f);
    if (ibase + il < FF) {
        v = *(const float4*)(coord + (size_t)c * FF * NF + (size_t)(ibase + il) * NF + f0);
    }
    s[il][f0 + 0] = v.x;
    s[il][f0 + 1] = v.y;
    s[il][f0 + 2] = v.z;
    s[il][f0 + 3] = v.w;
    __syncthreads();

    int i2 = t & 63;
    int fhi = t >> 6;  // 0..3
    #pragma unroll
    for (int pph = 0; pph < 4; pph++) {
        int f = pph * 4 + fhi;
        g_Xp[((size_t)f * DC + c) * IPAD + ibase + i2] = s[i2][f];
    }
}

// ---------------------------------------------------------------------------
// Per-filter syrk + distance epilogue (R3 scalar version, at ~96% of the
// FFMA issue roofline — DO NOT TOUCH).
// 128x128 tile / block, 256 threads, 8x8 per thread, k-step 8.
// Single strictly k-ascending FMA chain per output (bit-exact vs reference).
// ---------------------------------------------------------------------------
__global__ __launch_bounds__(256, 2) void gram_kernel() {
    const int f = blockIdx.z;

    // Decode linear upper-triangular tile index -> (ti, tj), ti <= tj
    int p = blockIdx.x;
    int ti = 0;
    while (p >= (16 - ti)) { p -= (16 - ti); ti++; }
    const int tj = ti + p;

    const float* X = g_Xp + (size_t)f * DC * IPAD;
    __shared__ float As[8][128];
    __shared__ float Bs[8][128];

    const int t  = threadIdx.x;
    const int kl = t >> 5;            // 0..7 smem row to fill
    const int i4 = (t & 31) << 2;     // float4 column offset
    const int tx = t & 15;
    const int ty = t >> 4;
    const int Ib = ti << 7;
    const int Jb = tj << 7;

    float acc[8][8];
    #pragma unroll
    for (int u = 0; u < 8; u++)
        #pragma unroll
        for (int v = 0; v < 8; v++) acc[u][v] = 0.0f;

    float4 ra = *(const float4*)(X + (size_t)kl * IPAD + Ib + i4);
    float4 rb = *(const float4*)(X + (size_t)kl * IPAD + Jb + i4);

    for (int k0 = 0; k0 < DC; k0 += 8) {
        *(float4*)&As[kl][i4] = ra;
        *(float4*)&Bs[kl][i4] = rb;
        __syncthreads();
        if (k0 + 8 < DC) {
            ra = *(const float4*)(X + (size_t)(k0 + 8 + kl) * IPAD + Ib + i4);
            rb = *(const float4*)(X + (size_t)(k0 + 8 + kl) * IPAD + Jb + i4);
        }
        #pragma unroll
        for (int kk = 0; kk < 8; kk++) {
            float a[8], b[8];
            *(float4*)&a[0] = *(const float4*)&As[kk][ty * 8];
            *(float4*)&a[4] = *(const float4*)&As[kk][ty * 8 + 4];
            *(float4*)&b[0] = *(const float4*)&Bs[kk][tx * 8];
            *(float4*)&b[4] = *(const float4*)&Bs[kk][tx * 8 + 4];
            #pragma unroll
            for (int u = 0; u < 8; u++)
                #pragma unroll
                for (int v = 0; v < 8; v++)
                    acc[u][v] = fmaf(a[u], b[v], acc[u][v]);
        }
        __syncthreads();
    }

    // Epilogue: dist = max(sq_i + sq_j - 2*G, 0). 2*acc is exact (power of 2),
    // identical rounding to the reference regardless of contraction.
    const int gib = Ib + ty * 8;
    const int gjb = Jb + tx * 8;
    #pragma unroll
    for (int u = 0; u < 8; u++) {
        int gi = gib + u;
        if (gi >= FF) continue;
        float si = g_sq[f * FF + gi];
        #pragma unroll
        for (int v = 0; v < 8; v++) {
            int gj = gjb + v;
            if (gj >= FF) continue;
            float sj = g_sq[f * FF + gj];
            float d = fmaxf(si + sj - 2.0f * acc[u][v], 0.0f);
            g_dist[((size_t)f * FF + gi) * FF + gj] = d;
            if (ti != tj)
                g_dist[((size_t)f * FF + gj) * FF + gi] = d;
        }
    }
}

// ---------------------------------------------------------------------------
// Top-8 smallest per row — 4 warps per row, TWO-STAGE exact merge.
// Scan: each warp covers a contiguous 500-element chunk, 4 staged float4
// loads per lane (MLP=4, small reg footprint); per-LANE top-8 via float
// fast-reject + u64 (dist_bits<<32|j) insertion (per-lane j ascends, so a
// tie can never displace — exact lax.top_k tie-break).
// Stage 1 (R7 bugfix): each warp merges its 32 per-lane top-8 arrays with
// the R3-proven 8-round warp-min + head extraction -> warp's true top-8,
// published to smem. Stage 2: warp 0 of each row extracts the global top-8
// from the 32 unique candidates. Output provably identical to the passing
// single-warp version. Block = 8 warps = 2 rows. No launch_bounds (R4 spill).
// ---------------------------------------------------------------------------
#define SENT_KEY 0x7F7FFFFFFFFFFFFFULL   // (FLT_MAX bits << 32) | 0xFFFFFFFF

__global__ void topk_kernel() {
    __shared__ unsigned long long cand[2][32];
    const int tid  = threadIdx.x;
    const int warp = tid >> 5;         // 0..7
    const int lane = tid & 31;
    const int rloc = warp >> 2;        // row within block (0..1)
    const int wir  = warp & 3;         // warp within row (0..3)
    const int row  = blockIdx.x * 2 + rloc;   // flat f*FF + i

    const float4* __restrict__ row4 = (const float4*)(g_dist + (size_t)row * FF);

    unsigned long long k[8];
    #pragma unroll
    for (int s = 0; s < 8; s++) k[s] = SENT_KEY;
    float k7f = 3.402823466e+38f;  // FLT_MAX

    // Stage: 4 float4 loads per lane, all issued before any consumption.
    // Chunk: float4 indices [wir*125, wir*125+125); iter grid 4x32 covers 128,
    // lanes with loc >= 125 get FLT_MAX padding (guard rejects). Every lane
    // sees >= 12 real elements, so all 8 key slots end up real.
    float4 d[4];
    int m4[4];
    #pragma unroll
    for (int it = 0; it < 4; it++) {
        int loc = it * 32 + lane;
        m4[it] = wir * 125 + loc;
        d[it] = (loc < 125) ? row4[m4[it]]
                            : make_float4(3.402823466e+38f, 3.402823466e+38f,
                                          3.402823466e+38f, 3.402823466e+38f);
    }

#define TOPK_TRY(dv, jv)                                                     \
    if ((dv) < k7f) {                                                        \
        unsigned long long key =                                             \
            ((unsigned long long)__float_as_uint(dv) << 32) | (unsigned)(jv);\
        k[7] = key;                                                          \
        _Pragma("unroll")                                                    \
        for (int s = 7; s > 0; s--) {                                        \
            if (k[s] < k[s - 1]) {                                           \
                unsigned long long tmp = k[s]; k[s] = k[s - 1]; k[s - 1] = tmp;\
            }                                                                \
        }                                                                    \
        k7f = __uint_as_float((unsigned)(k[7] >> 32));                       \
    }

    #pragma unroll
    for (int it = 0; it < 4; it++) {
        int j0 = m4[it] << 2;
        TOPK_TRY(d[it].x, j0 + 0);
        TOPK_TRY(d[it].y, j0 + 1);
        TOPK_TRY(d[it].z, j0 + 2);
        TOPK_TRY(d[it].w, j0 + 3);
    }
#undef TOPK_TRY

    // Stage 1: warp-level merge of the 32 per-lane top-8s (R3 extraction).
    {
        int head = 0;
        #pragma unroll
        for (int r = 0; r < KNN; r++) {
            unsigned long long v = (head < 8) ? k[head] : 0xFFFFFFFFFFFFFFFFULL;
            unsigned long long m = v;
            #pragma unroll
            for (int off = 16; off; off >>= 1) {
                unsigned long long o = __shfl_xor_sync(0xffffffffu, m, off);
                m = (o < m) ? o : m;
            }
            if (v == m) head++;  // keys unique (index embedded) -> one winner
            if (lane == 0)
                cand[rloc][wir * 8 + r] = m;
        }
    }
    __syncthreads();

    // Stage 2: warp 0 of each row extracts the global top-8 from the 32
    // unique, all-real candidates.
    if (wir == 0) {
        unsigned long long key = cand[rloc][lane];
        const int f = row / FF;
        const int i = row % FF;
        #pragma unroll
        for (int r = 0; r < KNN; r++) {
            unsigned long long m = key;
            #pragma unroll
            for (int off = 16; off; off >>= 1) {
                unsigned long long o = __shfl_xor_sync(0xffffffffu, m, off);
                m = (o < m) ? o : m;
            }
            if (key == m) key = 0xFFFFFFFFFFFFFFFFULL;  // unique -> one winner
            if (lane == 0)
                g_idx[(i * KNN + r) * NF + f] = (int)(m & 0xFFFFFFFFu);
        }
    }
}

// ---------------------------------------------------------------------------
// out[b][i*8+k][c] = inputs[b][ idx[i][k][c] ][c]
// ---------------------------------------------------------------------------
__global__ void gather_kernel(const float* __restrict__ inputs,
                              float* __restrict__ out) {
    int g = blockIdx.x * blockDim.x + threadIdx.x;
    const int total = NB * FF * KNN * NF;
    if (g >= total) return;
    int c   = g & 15;
    int row = (g >> 4) % (FF * KNN);
    int b   = g / (FF * KNN * NF);
    int r   = g_idx[row * NF + c];
    out[g] = inputs[((size_t)b * FF + r) * NF + c];
}

// ---------------------------------------------------------------------------
extern "C" void kernel_launch(void* const* d_in, const int* in_sizes, int n_in,
                              void* d_out, int out_size) {
    const float* inputs = (const float*)d_in[0];   // (64, 2000, 16)
    const float* coords = (const float*)d_in[1];   // (512, 2000, 16)
    if (n_in >= 2 && in_sizes[0] == DC * FF * NF) {
        coords = (const float*)d_in[0];
        inputs = (const float*)d_in[1];
    }

    sq_kernel<<<FF * NF / 32, 1024>>>(coords);
    pack_kernel<<<dim3(32, DC), 256>>>(coords);
    gram_kernel<<<dim3(136, 1, NF), 256>>>();
    topk_kernel<<<(NF * FF) / 2, 256>>>();
    gather_kernel<<<(NB * FF * KNN * NF) / 256, 256>>>(inputs, (float*)d_out);
}

// round 9
// speedup vs baseline: 2.6055x; 1.1355x over previous
#include <cuda_runtime.h>

#define NF 16        // filters
#define FF 2000      // features
#define DC 512       // coordinate (reduction) dim
#define NB 64        // batch
#define KNN 8        // neighbors
#define IPAD 2048    // padded feature dim for the packed operand

// Scratch (static device globals — no allocation at runtime)
__device__ float g_Xp[(size_t)NF * DC * IPAD];        // 64 MB packed [f][c][i]
__device__ float g_sq[NF * FF];                       // column squared norms
__device__ float g_dist[(size_t)NF * FF * FF];        // 256 MB distances [f][i][j]
__device__ int   g_idx[FF * KNN * NF];                // neighbor indices [(i*8+k)*16 + f]

// ---------------------------------------------------------------------------
// sq[f][i] = sum_c coord[c][i][f]^2, emulating XLA's GPU column-reduction
// order bit-exactly (DO NOT TOUCH — verified rel_err == 0.0):
//   partial[y] = sum_{m=0..15, ascending} fadd(p, fmul(x[y+32m], x[y+32m]))
//   result = shfl_down butterfly tree over y with offsets 16,8,4,2,1
// ---------------------------------------------------------------------------
__global__ __launch_bounds__(1024) void sq_kernel(const float* __restrict__ coord) {
    __shared__ float s[32][33];
    const int tx = threadIdx.x & 31;   // output lane (minor dim of (i,f) flat)
    const int ty = threadIdx.x >> 5;   // reduce lane
    const int outbase = blockIdx.x * 32;
    const int out = outbase + tx;      // flat index i*16 + f, 0..31999

    float acc = 0.0f;
    #pragma unroll
    for (int m = 0; m < 16; m++) {
        int c = ty + 32 * m;
        float v = coord[(size_t)c * (FF * NF) + out];
        acc = __fadd_rn(acc, __fmul_rn(v, v));
    }
    s[ty][tx] = acc;
    __syncthreads();

    float v = s[tx][ty];               // lane tx holds partial[tx] of output ty
    #pragma unroll
    for (int off = 16; off; off >>= 1)
        v = __fadd_rn(v, __shfl_down_sync(0xffffffffu, v, off));

    if (tx == 0) {
        int o = outbase + ty;          // flat i*16 + f
        int f = o & 15;
        int i = o >> 4;
        g_sq[f * FF + i] = v;
    }
}

// ---------------------------------------------------------------------------
// Pack coords (c, i, f) -> Xp[f][c][i], zero-padding i in [2000, 2048).
// ---------------------------------------------------------------------------
__global__ void pack_kernel(const float* __restrict__ coord) {
    __shared__ float s[64][17];  // padded to kill bank conflicts
    const int c = blockIdx.y;
    const int ibase = blockIdx.x * 64;
    const int t = threadIdx.x;

    int il = t >> 2;             // 0..63 local i
    int f0 = (t & 3) * 4;        // 0,4,8,12
    float4 v = make_float4(0.f, 0.f, 0.f, 0.f);
    if (ibase + il < FF) {
        v = *(const float4*)(coord + (size_t)c * FF * NF + (size_t)(ibase + il) * NF + f0);
    }
    s[il][f0 + 0] = v.x;
    s[il][f0 + 1] = v.y;
    s[il][f0 + 2] = v.z;
    s[il][f0 + 3] = v.w;
    __syncthreads();

    int i2 = t & 63;
    int fhi = t >> 6;  // 0..3
    #pragma unroll
    for (int pph = 0; pph < 4; pph++) {
        int f = pph * 4 + fhi;
        g_Xp[((size_t)f * DC + c) * IPAD + ibase + i2] = s[i2][f];
    }
}

// ---------------------------------------------------------------------------
// Per-filter syrk + distance epilogue (R3 scalar version, at ~91% of the
// FFMA issue roofline — DO NOT TOUCH).
// 128x128 tile / block, 256 threads, 8x8 per thread, k-step 8.
// Single strictly k-ascending FMA chain per output (bit-exact vs reference).
// ---------------------------------------------------------------------------
__global__ __launch_bounds__(256, 2) void gram_kernel() {
    const int f = blockIdx.z;

    // Decode linear upper-triangular tile index -> (ti, tj), ti <= tj
    int p = blockIdx.x;
    int ti = 0;
    while (p >= (16 - ti)) { p -= (16 - ti); ti++; }
    const int tj = ti + p;

    const float* X = g_Xp + (size_t)f * DC * IPAD;
    __shared__ float As[8][128];
    __shared__ float Bs[8][128];

    const int t  = threadIdx.x;
    const int kl = t >> 5;            // 0..7 smem row to fill
    const int i4 = (t & 31) << 2;     // float4 column offset
    const int tx = t & 15;
    const int ty = t >> 4;
    const int Ib = ti << 7;
    const int Jb = tj << 7;

    float acc[8][8];
    #pragma unroll
    for (int u = 0; u < 8; u++)
        #pragma unroll
        for (int v = 0; v < 8; v++) acc[u][v] = 0.0f;

    float4 ra = *(const float4*)(X + (size_t)kl * IPAD + Ib + i4);
    float4 rb = *(const float4*)(X + (size_t)kl * IPAD + Jb + i4);

    for (int k0 = 0; k0 < DC; k0 += 8) {
        *(float4*)&As[kl][i4] = ra;
        *(float4*)&Bs[kl][i4] = rb;
        __syncthreads();
        if (k0 + 8 < DC) {
            ra = *(const float4*)(X + (size_t)(k0 + 8 + kl) * IPAD + Ib + i4);
            rb = *(const float4*)(X + (size_t)(k0 + 8 + kl) * IPAD + Jb + i4);
        }
        #pragma unroll
        for (int kk = 0; kk < 8; kk++) {
            float a[8], b[8];
            *(float4*)&a[0] = *(const float4*)&As[kk][ty * 8];
            *(float4*)&a[4] = *(const float4*)&As[kk][ty * 8 + 4];
            *(float4*)&b[0] = *(const float4*)&Bs[kk][tx * 8];
            *(float4*)&b[4] = *(const float4*)&Bs[kk][tx * 8 + 4];
            #pragma unroll
            for (int u = 0; u < 8; u++)
                #pragma unroll
                for (int v = 0; v < 8; v++)
                    acc[u][v] = fmaf(a[u], b[v], acc[u][v]);
        }
        __syncthreads();
    }

    // Epilogue: dist = max(sq_i + sq_j - 2*G, 0). 2*acc is exact (power of 2),
    // identical rounding to the reference regardless of contraction.
    const int gib = Ib + ty * 8;
    const int gjb = Jb + tx * 8;
    #pragma unroll
    for (int u = 0; u < 8; u++) {
        int gi = gib + u;
        if (gi >= FF) continue;
        float si = g_sq[f * FF + gi];
        #pragma unroll
        for (int v = 0; v < 8; v++) {
            int gj = gjb + v;
            if (gj >= FF) continue;
            float sj = g_sq[f * FF + gj];
            float d = fmaxf(si + sj - 2.0f * acc[u][v], 0.0f);
            g_dist[((size_t)f * FF + gi) * FF + gj] = d;
            if (ti != tj)
                g_dist[((size_t)f * FF + gj) * FF + gi] = d;
        }
    }
}

// ---------------------------------------------------------------------------
// Top-8 smallest per row — back to R3's warp-per-row topology (best fill-tax
// amortization: 1 warp/row, ~63 elems/lane), upgraded with:
//   * manual 4x float4 staging per iteration (MLP=4, 16 staging regs — the
//     cheap form proven in R8, not R6's 178-reg scalar blowup)
//   * float-only fast-reject guard (R8-proven rel_err=0; per-lane j strictly
//     ascends so a tie can never displace — exact lax.top_k tie-break)
//   * 128-thread blocks for occupancy headroom
// Merge: R3's 8-round warp-min + head extraction, unchanged.
// No launch_bounds (R4 spill lesson).
// ---------------------------------------------------------------------------
#define SENT_KEY 0x7F7FFFFFFFFFFFFFULL   // (FLT_MAX bits << 32) | 0xFFFFFFFF
#define FMAXV    3.402823466e+38f

__global__ void topk_kernel() {
    const int warp = (blockIdx.x * blockDim.x + threadIdx.x) >> 5;
    const int lane = threadIdx.x & 31;
    if (warp >= NF * FF) return;

    const float4* __restrict__ row4 = (const float4*)(g_dist + (size_t)warp * FF);

    unsigned long long k[8];
    #pragma unroll
    for (int s = 0; s < 8; s++) k[s] = SENT_KEY;
    float k7f = FMAXV;

#define TOPK_TRY(dv, jv)                                                     \
    if ((dv) < k7f) {                                                        \
        unsigned long long key =                                             \
            ((unsigned long long)__float_as_uint(dv) << 32) | (unsigned)(jv);\
        k[7] = key;                                                         \
        _Pragma("unroll")                                                    \
        for (int s = 7; s > 0; s--) {                                        \
            if (k[s] < k[s - 1]) {                                           \
                unsigned long long tmp = k[s]; k[s] = k[s - 1]; k[s - 1] = tmp;\
            }                                                                \
        }                                                                    \
        k7f = __uint_as_float((unsigned)(k[7] >> 32));                       \
    }

    // Row = 500 float4. 4 iterations of (stage 4 loads; process 16 elems).
    // Taps base + {0,32,64,96} + lane; per-lane j ascends monotonically.
    #pragma unroll
    for (int base = 0; base < 500; base += 128) {
        float4 d[4];
        int m4[4];
        #pragma unroll
        for (int t = 0; t < 4; t++) {
            m4[t] = base + t * 32 + lane;
            d[t] = (m4[t] < 500) ? row4[m4[t]]
                                 : make_float4(FMAXV, FMAXV, FMAXV, FMAXV);
        }
        #pragma unroll
        for (int t = 0; t < 4; t++) {
            int j0 = m4[t] << 2;
            TOPK_TRY(d[t].x, j0 + 0);
            TOPK_TRY(d[t].y, j0 + 1);
            TOPK_TRY(d[t].z, j0 + 2);
            TOPK_TRY(d[t].w, j0 + 3);
        }
    }
#undef TOPK_TRY

    const int f = warp / FF;
    const int i = warp % FF;

    int head = 0;
    for (int r = 0; r < KNN; r++) {
        unsigned long long v = (head < 8) ? k[head] : 0xFFFFFFFFFFFFFFFFULL;
        unsigned long long m = v;
        #pragma unroll
        for (int off = 16; off; off >>= 1) {
            unsigned long long o = __shfl_xor_sync(0xffffffffu, m, off);
            m = (o < m) ? o : m;
        }
        if (v == m) head++;  // keys unique (index embedded) -> single winner
        if (lane == 0)
            g_idx[(i * KNN + r) * NF + f] = (int)(m & 0xFFFFFFFFu);
    }
}

// ---------------------------------------------------------------------------
// out[b][i*8+k][c] = inputs[b][ idx[i][k][c] ][c]
// ---------------------------------------------------------------------------
__global__ void gather_kernel(const float* __restrict__ inputs,
                              float* __restrict__ out) {
    int g = blockIdx.x * blockDim.x + threadIdx.x;
    const int total = NB * FF * KNN * NF;
    if (g >= total) return;
    int c   = g & 15;
    int row = (g >> 4) % (FF * KNN);
    int b   = g / (FF * KNN * NF);
    int r   = g_idx[row * NF + c];
    out[g] = inputs[((size_t)b * FF + r) * NF + c];
}

// ---------------------------------------------------------------------------
extern "C" void kernel_launch(void* const* d_in, const int* in_sizes, int n_in,
                              void* d_out, int out_size) {
    const float* inputs = (const float*)d_in[0];   // (64, 2000, 16)
    const float* coords = (const float*)d_in[1];   // (512, 2000, 16)
    if (n_in >= 2 && in_sizes[0] == DC * FF * NF) {
        coords = (const float*)d_in[0];
        inputs = (const float*)d_in[1];
    }

    sq_kernel<<<FF * NF / 32, 1024>>>(coords);
    pack_kernel<<<dim3(32, DC), 256>>>(coords);
    gram_kernel<<<dim3(136, 1, NF), 256>>>();
    topk_kernel<<<(NF * FF) / 4, 128>>>();
    gather_kernel<<<(NB * FF * KNN * NF) / 256, 256>>>(inputs, (float*)d_out);
}

// round 10
// speedup vs baseline: 3.2225x; 1.2368x over previous
#include <cuda_runtime.h>

#define NF 16        // filters
#define FF 2000      // features
#define DC 512       // coordinate (reduction) dim
#define NB 64        // batch
#define KNN 8        // neighbors
#define IPAD 2048    // padded feature dim for the packed operand

// Scratch (static device globals — no allocation at runtime)
__device__ float g_Xp[(size_t)NF * DC * IPAD];        // 64 MB packed [f][c][i]
__device__ float g_sq[NF * FF];                       // column squared norms
__device__ float g_dist[(size_t)NF * FF * FF];        // 256 MB distances [f][i][j]
__device__ int   g_idx[FF * KNN * NF];                // neighbor indices [(i*8+k)*16 + f]

// ---------------------------------------------------------------------------
// sq[f][i] = sum_c coord[c][i][f]^2, emulating XLA's GPU column-reduction
// order bit-exactly (DO NOT TOUCH — verified rel_err == 0.0).
// ---------------------------------------------------------------------------
__global__ __launch_bounds__(1024) void sq_kernel(const float* __restrict__ coord) {
    __shared__ float s[32][33];
    const int tx = threadIdx.x & 31;
    const int ty = threadIdx.x >> 5;
    const int outbase = blockIdx.x * 32;
    const int out = outbase + tx;

    float acc = 0.0f;
    #pragma unroll
    for (int m = 0; m < 16; m++) {
        int c = ty + 32 * m;
        float v = coord[(size_t)c * (FF * NF) + out];
        acc = __fadd_rn(acc, __fmul_rn(v, v));
    }
    s[ty][tx] = acc;
    __syncthreads();

    float v = s[tx][ty];
    #pragma unroll
    for (int off = 16; off; off >>= 1)
        v = __fadd_rn(v, __shfl_down_sync(0xffffffffu, v, off));

    if (tx == 0) {
        int o = outbase + ty;
        int f = o & 15;
        int i = o >> 4;
        g_sq[f * FF + i] = v;
    }
}

// ---------------------------------------------------------------------------
// Pack coords (c, i, f) -> Xp[f][c][i], zero-padding i in [2000, 2048).
// ---------------------------------------------------------------------------
__global__ void pack_kernel(const float* __restrict__ coord) {
    __shared__ float s[64][17];
    const int c = blockIdx.y;
    const int ibase = blockIdx.x * 64;
    const int t = threadIdx.x;

    int il = t >> 2;
    int f0 = (t & 3) * 4;
    float4 v = make_float4(0.f, 0.f, 0.f, 0.f);
    if (ibase + il < FF) {
        v = *(const float4*)(coord + (size_t)c * FF * NF + (size_t)(ibase + il) * NF + f0);
    }
    s[il][f0 + 0] = v.x;
    s[il][f0 + 1] = v.y;
    s[il][f0 + 2] = v.z;
    s[il][f0 + 3] = v.w;
    __syncthreads();

    int i2 = t & 63;
    int fhi = t >> 6;
    #pragma unroll
    for (int pph = 0; pph < 4; pph++) {
        int f = pph * 4 + fhi;
        g_Xp[((size_t)f * DC + c) * IPAD + ibase + i2] = s[i2][f];
    }
}

// ---------------------------------------------------------------------------
// Per-filter syrk + distance epilogue (bit-exact, near FFMA roofline —
// DO NOT TOUCH).
// ---------------------------------------------------------------------------
__global__ __launch_bounds__(256, 2) void gram_kernel() {
    const int f = blockIdx.z;

    int p = blockIdx.x;
    int ti = 0;
    while (p >= (16 - ti)) { p -= (16 - ti); ti++; }
    const int tj = ti + p;

    const float* X = g_Xp + (size_t)f * DC * IPAD;
    __shared__ float As[8][128];
    __shared__ float Bs[8][128];

    const int t  = threadIdx.x;
    const int kl = t >> 5;
    const int i4 = (t & 31) << 2;
    const int tx = t & 15;
    const int ty = t >> 4;
    const int Ib = ti << 7;
    const int Jb = tj << 7;

    float acc[8][8];
    #pragma unroll
    for (int u = 0; u < 8; u++)
        #pragma unroll
        for (int v = 0; v < 8; v++) acc[u][v] = 0.0f;

    float4 ra = *(const float4*)(X + (size_t)kl * IPAD + Ib + i4);
    float4 rb = *(const float4*)(X + (size_t)kl * IPAD + Jb + i4);

    for (int k0 = 0; k0 < DC; k0 += 8) {
        *(float4*)&As[kl][i4] = ra;
        *(float4*)&Bs[kl][i4] = rb;
        __syncthreads();
        if (k0 + 8 < DC) {
            ra = *(const float4*)(X + (size_t)(k0 + 8 + kl) * IPAD + Ib + i4);
            rb = *(const float4*)(X + (size_t)(k0 + 8 + kl) * IPAD + Jb + i4);
        }
        #pragma unroll
        for (int kk = 0; kk < 8; kk++) {
            float a[8], b[8];
            *(float4*)&a[0] = *(const float4*)&As[kk][ty * 8];
            *(float4*)&a[4] = *(const float4*)&As[kk][ty * 8 + 4];
            *(float4*)&b[0] = *(const float4*)&Bs[kk][tx * 8];
            *(float4*)&b[4] = *(const float4*)&Bs[kk][tx * 8 + 4];
            #pragma unroll
            for (int u = 0; u < 8; u++)
                #pragma unroll
                for (int v = 0; v < 8; v++)
                    acc[u][v] = fmaf(a[u], b[v], acc[u][v]);
        }
        __syncthreads();
    }

    const int gib = Ib + ty * 8;
    const int gjb = Jb + tx * 8;
    #pragma unroll
    for (int u = 0; u < 8; u++) {
        int gi = gib + u;
        if (gi >= FF) continue;
        float si = g_sq[f * FF + gi];
        #pragma unroll
        for (int v = 0; v < 8; v++) {
            int gj = gjb + v;
            if (gj >= FF) continue;
            float sj = g_sq[f * FF + gj];
            float d = fmaxf(si + sj - 2.0f * acc[u][v], 0.0f);
            g_dist[((size_t)f * FF + gi) * FF + gj] = d;
            if (ti != tj)
                g_dist[((size_t)f * FF + gj) * FF + gi] = d;
        }
    }
}

// ---------------------------------------------------------------------------
// Top-8 smallest per row — warp per row, NAMED-REGISTER buffer + warp-shared
// threshold.
//   * k0..k7: named u64 scalars (sorted ascending). No arrays, no dynamic
//     indexing anywhere -> ptxas cannot demote to local memory (the L1~85%
//     pathology of R4/R8/R9).
//   * Exact u64 keys (dist_bits<<32 | j): lax.top_k tie-break preserved.
//   * Warp threshold: Tval = warp-min over lanes of value(k7). Any lane's k7
//     bounds the global 8th (8 genuine elements <= it), so rejecting
//     d > Tval is provably safe; ties (d == Tval) pass to the exact insert.
//     After batch 1 this kills ~98% of insert attempts.
//   * 4x float4 staging per batch (MLP=4), FMNMX min-of-4 pre-filter.
// Extraction: head-shift (static) + 8-round warp-min, output identical to R3.
// ---------------------------------------------------------------------------
#define SENT_KEY 0x7F7FFFFFFFFFFFFFULL   // (FLT_MAX bits << 32) | 0xFFFFFFFF
#define FMAXV    3.402823466e+38f

__global__ void topk_kernel() {
    const int warp = (blockIdx.x * blockDim.x + threadIdx.x) >> 5;
    const int lane = threadIdx.x & 31;
    if (warp >= NF * FF) return;

    const float4* __restrict__ row4 = (const float4*)(g_dist + (size_t)warp * FF);

    unsigned long long k0 = SENT_KEY, k1 = SENT_KEY, k2 = SENT_KEY,
                       k3 = SENT_KEY, k4 = SENT_KEY, k5 = SENT_KEY,
                       k6 = SENT_KEY, k7 = SENT_KEY;
    float Tval = FMAXV;

    // ascending order k0 <= ... <= k7; CSW(a,b): enforce a <= b
#define CSW(a, b) { if ((b) < (a)) { unsigned long long _t = (a); (a) = (b); (b) = _t; } }
#define TOPK_TRY(dv, jv)                                                      \
    if ((dv) <= Tval) {                                                       \
        unsigned long long key =                                              \
            ((unsigned long long)__float_as_uint(dv) << 32) | (unsigned)(jv); \
        if (key < k7) {                                                       \
            k7 = key;                                                         \
            CSW(k6, k7); CSW(k5, k6); CSW(k4, k5); CSW(k3, k4);               \
            CSW(k2, k3); CSW(k1, k2); CSW(k0, k1);                            \
        }                                                                     \
    }

    // Row = 500 float4; 4 batches of (stage 4 float4/lane; filter; try).
    #pragma unroll
    for (int base = 0; base < 500; base += 128) {
        float4 d[4];
        int m4[4];
        #pragma unroll
        for (int t = 0; t < 4; t++) {
            m4[t] = base + t * 32 + lane;
            d[t] = (m4[t] < 500) ? row4[m4[t]]
                                 : make_float4(FMAXV, FMAXV, FMAXV, FMAXV);
        }
        #pragma unroll
        for (int t = 0; t < 4; t++) {
            float mn = fminf(fminf(d[t].x, d[t].y), fminf(d[t].z, d[t].w));
            if (mn <= Tval) {
                int j0 = m4[t] << 2;
                TOPK_TRY(d[t].x, j0 + 0);
                TOPK_TRY(d[t].y, j0 + 1);
                TOPK_TRY(d[t].z, j0 + 2);
                TOPK_TRY(d[t].w, j0 + 3);
            }
        }
        // Tighten the shared threshold: Tval = warp-min of value(k7).
        // Valid once >= 1 lane holds 8 genuine elements (true after batch 1;
        // before that lanes report FLT_MAX, keeping Tval = FLT_MAX).
        float th = __uint_as_float((unsigned)(k7 >> 32));
        #pragma unroll
        for (int off = 16; off; off >>= 1)
            th = fminf(th, __shfl_xor_sync(0xffffffffu, th, off));
        Tval = th;
    }
#undef TOPK_TRY
#undef CSW

    const int f = warp / FF;
    const int i = warp % FF;

    // Extraction: global min over lane heads (k0); winner shifts its buffer.
    // All static indexing; keys unique (index embedded) -> single winner.
    #pragma unroll
    for (int r = 0; r < KNN; r++) {
        unsigned long long m = k0;
        #pragma unroll
        for (int off = 16; off; off >>= 1) {
            unsigned long long o = __shfl_xor_sync(0xffffffffu, m, off);
            m = (o < m) ? o : m;
        }
        if (k0 == m) {
            k0 = k1; k1 = k2; k2 = k3; k3 = k4;
            k4 = k5; k5 = k6; k6 = k7; k7 = 0xFFFFFFFFFFFFFFFFULL;
        }
        if (lane == 0)
            g_idx[(i * KNN + r) * NF + f] = (int)(m & 0xFFFFFFFFu);
    }
}

// ---------------------------------------------------------------------------
// out[b][i*8+k][c] = inputs[b][ idx[i][k][c] ][c]
// ---------------------------------------------------------------------------
__global__ void gather_kernel(const float* __restrict__ inputs,
                              float* __restrict__ out) {
    int g = blockIdx.x * blockDim.x + threadIdx.x;
    const int total = NB * FF * KNN * NF;
    if (g >= total) return;
    int c   = g & 15;
    int row = (g >> 4) % (FF * KNN);
    int b   = g / (FF * KNN * NF);
    int r   = g_idx[row * NF + c];
    out[g] = inputs[((size_t)b * FF + r) * NF + c];
}

// ---------------------------------------------------------------------------
extern "C" void kernel_launch(void* const* d_in, const int* in_sizes, int n_in,
                              void* d_out, int out_size) {
    const float* inputs = (const float*)d_in[0];   // (64, 2000, 16)
    const float* coords = (const float*)d_in[1];   // (512, 2000, 16)
    if (n_in >= 2 && in_sizes[0] == DC * FF * NF) {
        coords = (const float*)d_in[0];
        inputs = (const float*)d_in[1];
    }

    sq_kernel<<<FF * NF / 32, 1024>>>(coords);
    pack_kernel<<<dim3(32, DC), 256>>>(coords);
    gram_kernel<<<dim3(136, 1, NF), 256>>>();
    topk_kernel<<<(NF * FF) / 4, 128>>>();
    gather_kernel<<<(NB * FF * KNN * NF) / 256, 256>>>(inputs, (float*)d_out);
}

// round 11
// speedup vs baseline: 3.7416x; 1.1611x over previous
#include <cuda_runtime.h>

#define NF 16        // filters
#define FF 2000      // features
#define DC 512       // coordinate (reduction) dim
#define NB 64        // batch
#define KNN 8        // neighbors
#define IPAD 2048    // padded feature dim for the packed operand

// Scratch (static device globals — no allocation at runtime)
__device__ float g_Xp[(size_t)NF * DC * IPAD];        // 64 MB packed [f][c][i]
__device__ float g_sq[NF * FF];                       // column squared norms
__device__ float g_dist[(size_t)NF * FF * FF];        // 256 MB distances [f][i][j]
__device__ int   g_idx[FF * KNN * NF];                // neighbor indices [(i*8+k)*16 + f]

// ---------------------------------------------------------------------------
// sq[f][i] = sum_c coord[c][i][f]^2, emulating XLA's GPU column-reduction
// order bit-exactly (DO NOT TOUCH — verified rel_err == 0.0).
// ---------------------------------------------------------------------------
__global__ __launch_bounds__(1024) void sq_kernel(const float* __restrict__ coord) {
    __shared__ float s[32][33];
    const int tx = threadIdx.x & 31;
    const int ty = threadIdx.x >> 5;
    const int outbase = blockIdx.x * 32;
    const int out = outbase + tx;

    float acc = 0.0f;
    #pragma unroll
    for (int m = 0; m < 16; m++) {
        int c = ty + 32 * m;
        float v = coord[(size_t)c * (FF * NF) + out];
        acc = __fadd_rn(acc, __fmul_rn(v, v));
    }
    s[ty][tx] = acc;
    __syncthreads();

    float v = s[tx][ty];
    #pragma unroll
    for (int off = 16; off; off >>= 1)
        v = __fadd_rn(v, __shfl_down_sync(0xffffffffu, v, off));

    if (tx == 0) {
        int o = outbase + ty;
        int f = o & 15;
        int i = o >> 4;
        g_sq[f * FF + i] = v;
    }
}

// ---------------------------------------------------------------------------
// Pack coords (c, i, f) -> Xp[f][c][i], zero-padding i in [2000, 2048).
// ---------------------------------------------------------------------------
__global__ void pack_kernel(const float* __restrict__ coord) {
    __shared__ float s[64][17];
    const int c = blockIdx.y;
    const int ibase = blockIdx.x * 64;
    const int t = threadIdx.x;

    int il = t >> 2;
    int f0 = (t & 3) * 4;
    float4 v = make_float4(0.f, 0.f, 0.f, 0.f);
    if (ibase + il < FF) {
        v = *(const float4*)(coord + (size_t)c * FF * NF + (size_t)(ibase + il) * NF + f0);
    }
    s[il][f0 + 0] = v.x;
    s[il][f0 + 1] = v.y;
    s[il][f0 + 2] = v.z;
    s[il][f0 + 3] = v.w;
    __syncthreads();

    int i2 = t & 63;
    int fhi = t >> 6;
    #pragma unroll
    for (int pph = 0; pph < 4; pph++) {
        int f = pph * 4 + fhi;
        g_Xp[((size_t)f * DC + c) * IPAD + ibase + i2] = s[i2][f];
    }
}

// ---------------------------------------------------------------------------
// Per-filter syrk + distance epilogue (bit-exact, at the scalar-FFMA issue
// roofline — DO NOT TOUCH).
// ---------------------------------------------------------------------------
__global__ __launch_bounds__(256, 2) void gram_kernel() {
    const int f = blockIdx.z;

    int p = blockIdx.x;
    int ti = 0;
    while (p >= (16 - ti)) { p -= (16 - ti); ti++; }
    const int tj = ti + p;

    const float* X = g_Xp + (size_t)f * DC * IPAD;
    __shared__ float As[8][128];
    __shared__ float Bs[8][128];

    const int t  = threadIdx.x;
    const int kl = t >> 5;
    const int i4 = (t & 31) << 2;
    const int tx = t & 15;
    const int ty = t >> 4;
    const int Ib = ti << 7;
    const int Jb = tj << 7;

    float acc[8][8];
    #pragma unroll
    for (int u = 0; u < 8; u++)
        #pragma unroll
        for (int v = 0; v < 8; v++) acc[u][v] = 0.0f;

    float4 ra = *(const float4*)(X + (size_t)kl * IPAD + Ib + i4);
    float4 rb = *(const float4*)(X + (size_t)kl * IPAD + Jb + i4);

    for (int k0 = 0; k0 < DC; k0 += 8) {
        *(float4*)&As[kl][i4] = ra;
        *(float4*)&Bs[kl][i4] = rb;
        __syncthreads();
        if (k0 + 8 < DC) {
            ra = *(const float4*)(X + (size_t)(k0 + 8 + kl) * IPAD + Ib + i4);
            rb = *(const float4*)(X + (size_t)(k0 + 8 + kl) * IPAD + Jb + i4);
        }
        #pragma unroll
        for (int kk = 0; kk < 8; kk++) {
            float a[8], b[8];
            *(float4*)&a[0] = *(const float4*)&As[kk][ty * 8];
            *(float4*)&a[4] = *(const float4*)&As[kk][ty * 8 + 4];
            *(float4*)&b[0] = *(const float4*)&Bs[kk][tx * 8];
            *(float4*)&b[4] = *(const float4*)&Bs[kk][tx * 8 + 4];
            #pragma unroll
            for (int u = 0; u < 8; u++)
                #pragma unroll
                for (int v = 0; v < 8; v++)
                    acc[u][v] = fmaf(a[u], b[v], acc[u][v]);
        }
        __syncthreads();
    }

    const int gib = Ib + ty * 8;
    const int gjb = Jb + tx * 8;
    #pragma unroll
    for (int u = 0; u < 8; u++) {
        int gi = gib + u;
        if (gi >= FF) continue;
        float si = g_sq[f * FF + gi];
        #pragma unroll
        for (int v = 0; v < 8; v++) {
            int gj = gjb + v;
            if (gj >= FF) continue;
            float sj = g_sq[f * FF + gj];
            float d = fmaxf(si + sj - 2.0f * acc[u][v], 0.0f);
            g_dist[((size_t)f * FF + gi) * FF + gj] = d;
            if (ti != tj)
                g_dist[((size_t)f * FF + gj) * FF + gi] = d;
        }
    }
}

// ---------------------------------------------------------------------------
// Top-8 smallest per row — warp per row, TWO-PASS with sampled threshold.
// Pass A (FMNMX only): per-lane min over its ~62 elements; then T = 8th-
//   smallest of the 32 lane minima via 8 warp-min-retire rounds.
//   Soundness: the 8 retired minima are 8 distinct row elements <= T, so the
//   global 8th-smallest d8 <= T; tie-collapse only raises T (still valid).
// Pass B: exact u64 (dist_bits<<32|j) insert ONLY for d <= T (~10-15 accepts
//   per ROW — fill tax gone). Row is L1-resident from pass A. Named-register
//   buffer k0..k7 (no arrays -> no local-memory demotion, R10 lesson).
//   A lane's buffer keeps its 8 smallest keys, and global top-8 members in a
//   lane are among its lane-top-8, so overflow is safe.
// Extraction: head-shift + 8-round warp-min — byte-identical to R10 (exact
// lax.top_k tie-break, rel_err 0.0 proven).
// ---------------------------------------------------------------------------
#define SENT_KEY 0x7F7FFFFFFFFFFFFFULL   // (FLT_MAX bits << 32) | 0xFFFFFFFF
#define FMAXV    3.402823466e+38f

__global__ void topk_kernel() {
    const int warp = (blockIdx.x * blockDim.x + threadIdx.x) >> 5;
    const int lane = threadIdx.x & 31;
    if (warp >= NF * FF) return;

    const float4* __restrict__ row4 = (const float4*)(g_dist + (size_t)warp * FF);

    // ---- Pass A: per-lane min (staged loads, MLP=4) ----
    float lmin = FMAXV;
    #pragma unroll
    for (int base = 0; base < 500; base += 128) {
        float4 d[4];
        #pragma unroll
        for (int t = 0; t < 4; t++) {
            int m = base + t * 32 + lane;
            d[t] = (m < 500) ? row4[m]
                             : make_float4(FMAXV, FMAXV, FMAXV, FMAXV);
        }
        #pragma unroll
        for (int t = 0; t < 4; t++)
            lmin = fminf(lmin, fminf(fminf(d[t].x, d[t].y),
                                     fminf(d[t].z, d[t].w)));
    }

    // T = 8th-smallest lane minimum (warp-min with retire; ties over-retire,
    // which only raises T — still a valid upper bound on d8).
    float T;
    {
        float mv = lmin;
        #pragma unroll
        for (int r = 0; r < KNN; r++) {
            float m = mv;
            #pragma unroll
            for (int off = 16; off; off >>= 1)
                m = fminf(m, __shfl_xor_sync(0xffffffffu, m, off));
            T = m;
            if (mv == m) mv = FMAXV;   // retire winner(s)
        }
    }

    // ---- Pass B: exact insert of elements <= T (L1-resident reload) ----
    unsigned long long k0 = SENT_KEY, k1 = SENT_KEY, k2 = SENT_KEY,
                       k3 = SENT_KEY, k4 = SENT_KEY, k5 = SENT_KEY,
                       k6 = SENT_KEY, k7 = SENT_KEY;

#define CSW(a, b) { if ((b) < (a)) { unsigned long long _t = (a); (a) = (b); (b) = _t; } }
#define TOPK_TRY(dv, jv)                                                      \
    if ((dv) <= T) {                                                          \
        unsigned long long key =                                              \
            ((unsigned long long)__float_as_uint(dv) << 32) | (unsigned)(jv); \
        if (key < k7) {                                                       \
            k7 = key;                                                         \
            CSW(k6, k7); CSW(k5, k6); CSW(k4, k5); CSW(k3, k4);               \
            CSW(k2, k3); CSW(k1, k2); CSW(k0, k1);                            \
        }                                                                     \
    }

    #pragma unroll
    for (int base = 0; base < 500; base += 128) {
        float4 d[4];
        int m4[4];
        #pragma unroll
        for (int t = 0; t < 4; t++) {
            m4[t] = base + t * 32 + lane;
            d[t] = (m4[t] < 500) ? row4[m4[t]]
                                 : make_float4(FMAXV, FMAXV, FMAXV, FMAXV);
        }
        #pragma unroll
        for (int t = 0; t < 4; t++) {
            float mn = fminf(fminf(d[t].x, d[t].y), fminf(d[t].z, d[t].w));
            if (mn <= T) {
                int j0 = m4[t] << 2;
                TOPK_TRY(d[t].x, j0 + 0);
                TOPK_TRY(d[t].y, j0 + 1);
                TOPK_TRY(d[t].z, j0 + 2);
                TOPK_TRY(d[t].w, j0 + 3);
            }
        }
    }
#undef TOPK_TRY
#undef CSW

    const int f = warp / FF;
    const int i = warp % FF;

    // Extraction: global min over lane heads (k0); winner shifts its buffer.
    // All static indexing; keys unique (index embedded) -> single winner.
    #pragma unroll
    for (int r = 0; r < KNN; r++) {
        unsigned long long m = k0;
        #pragma unroll
        for (int off = 16; off; off >>= 1) {
            unsigned long long o = __shfl_xor_sync(0xffffffffu, m, off);
            m = (o < m) ? o : m;
        }
        if (k0 == m) {
            k0 = k1; k1 = k2; k2 = k3; k3 = k4;
            k4 = k5; k5 = k6; k6 = k7; k7 = 0xFFFFFFFFFFFFFFFFULL;
        }
        if (lane == 0)
            g_idx[(i * KNN + r) * NF + f] = (int)(m & 0xFFFFFFFFu);
    }
}

// ---------------------------------------------------------------------------
// out[b][i*8+k][c] = inputs[b][ idx[i][k][c] ][c]
// ---------------------------------------------------------------------------
__global__ void gather_kernel(const float* __restrict__ inputs,
                              float* __restrict__ out) {
    int g = blockIdx.x * blockDim.x + threadIdx.x;
    const int total = NB * FF * KNN * NF;
    if (g >= total) return;
    int c   = g & 15;
    int row = (g >> 4) % (FF * KNN);
    int b   = g / (FF * KNN * NF);
    int r   = g_idx[row * NF + c];
    out[g] = inputs[((size_t)b * FF + r) * NF + c];
}

// ---------------------------------------------------------------------------
extern "C" void kernel_launch(void* const* d_in, const int* in_sizes, int n_in,
                              void* d_out, int out_size) {
    const float* inputs = (const float*)d_in[0];   // (64, 2000, 16)
    const float* coords = (const float*)d_in[1];   // (512, 2000, 16)
    if (n_in >= 2 && in_sizes[0] == DC * FF * NF) {
        coords = (const float*)d_in[0];
        inputs = (const float*)d_in[1];
    }

    sq_kernel<<<FF * NF / 32, 1024>>>(coords);
    pack_kernel<<<dim3(32, DC), 256>>>(coords);
    gram_kernel<<<dim3(136, 1, NF), 256>>>();
    topk_kernel<<<(NF * FF) / 4, 128>>>();
    gather_kernel<<<(NB * FF * KNN * NF) / 256, 256>>>(inputs, (float*)d_out);
}

// round 13
// speedup vs baseline: 3.7918x; 1.0134x over previous
#include <cuda_runtime.h>

#define NF 16        // filters
#define FF 2000      // features
#define DC 512       // coordinate (reduction) dim
#define NB 64        // batch
#define KNN 8        // neighbors
#define IPAD 2048    // padded feature dim for the packed operand

// Scratch (static device globals — no allocation at runtime)
__device__ float g_Xp[(size_t)NF * DC * IPAD];        // 64 MB packed [f][c][i]
__device__ float g_sq[NF * FF];                       // column squared norms
__device__ float g_dist[(size_t)NF * FF * FF];        // 256 MB distances [f][i][j]
__device__ int   g_idx[FF * KNN * NF];                // neighbor indices [(i*8+k)*16 + f]

// ---------------------------------------------------------------------------
// sq[f][i] = sum_c coord[c][i][f]^2, emulating XLA's GPU column-reduction
// order bit-exactly (DO NOT TOUCH — verified rel_err == 0.0).
// ---------------------------------------------------------------------------
__global__ __launch_bounds__(1024) void sq_kernel(const float* __restrict__ coord) {
    __shared__ float s[32][33];
    const int tx = threadIdx.x & 31;
    const int ty = threadIdx.x >> 5;
    const int outbase = blockIdx.x * 32;
    const int out = outbase + tx;

    float acc = 0.0f;
    #pragma unroll
    for (int m = 0; m < 16; m++) {
        int c = ty + 32 * m;
        float v = coord[(size_t)c * (FF * NF) + out];
        acc = __fadd_rn(acc, __fmul_rn(v, v));
    }
    s[ty][tx] = acc;
    __syncthreads();

    float v = s[tx][ty];
    #pragma unroll
    for (int off = 16; off; off >>= 1)
        v = __fadd_rn(v, __shfl_down_sync(0xffffffffu, v, off));

    if (tx == 0) {
        int o = outbase + ty;
        int f = o & 15;
        int i = o >> 4;
        g_sq[f * FF + i] = v;
    }
}

// ---------------------------------------------------------------------------
// Pack coords (c, i, f) -> Xp[f][c][i], zero-padding i in [2000, 2048).
// ---------------------------------------------------------------------------
__global__ void pack_kernel(const float* __restrict__ coord) {
    __shared__ float s[64][17];
    const int c = blockIdx.y;
    const int ibase = blockIdx.x * 64;
    const int t = threadIdx.x;

    int il = t >> 2;
    int f0 = (t & 3) * 4;
    float4 v = make_float4(0.f, 0.f, 0.f, 0.f);
    if (ibase + il < FF) {
        v = *(const float4*)(coord + (size_t)c * FF * NF + (size_t)(ibase + il) * NF + f0);
    }
    s[il][f0 + 0] = v.x;
    s[il][f0 + 1] = v.y;
    s[il][f0 + 2] = v.z;
    s[il][f0 + 3] = v.w;
    __syncthreads();

    int i2 = t & 63;
    int fhi = t >> 6;
    #pragma unroll
    for (int pph = 0; pph < 4; pph++) {
        int f = pph * 4 + fhi;
        g_Xp[((size_t)f * DC + c) * IPAD + ibase + i2] = s[i2][f];
    }
}

// ---------------------------------------------------------------------------
// Per-filter syrk + distance epilogue (bit-exact, at the scalar-FFMA issue
// roofline; filter = fbase + blockIdx.z for chunked pipelining).
// ---------------------------------------------------------------------------
__global__ __launch_bounds__(256, 2) void gram_kernel(int fbase) {
    const int f = fbase + blockIdx.z;

    int p = blockIdx.x;
    int ti = 0;
    while (p >= (16 - ti)) { p -= (16 - ti); ti++; }
    const int tj = ti + p;

    const float* X = g_Xp + (size_t)f * DC * IPAD;
    __shared__ float As[8][128];
    __shared__ float Bs[8][128];

    const int t  = threadIdx.x;
    const int kl = t >> 5;
    const int i4 = (t & 31) << 2;
    const int tx = t & 15;
    const int ty = t >> 4;
    const int Ib = ti << 7;
    const int Jb = tj << 7;

    float acc[8][8];
    #pragma unroll
    for (int u = 0; u < 8; u++)
        #pragma unroll
        for (int v = 0; v < 8; v++) acc[u][v] = 0.0f;

    float4 ra = *(const float4*)(X + (size_t)kl * IPAD + Ib + i4);
    float4 rb = *(const float4*)(X + (size_t)kl * IPAD + Jb + i4);

    for (int k0 = 0; k0 < DC; k0 += 8) {
        *(float4*)&As[kl][i4] = ra;
        *(float4*)&Bs[kl][i4] = rb;
        __syncthreads();
        if (k0 + 8 < DC) {
            ra = *(const float4*)(X + (size_t)(k0 + 8 + kl) * IPAD + Ib + i4);
            rb = *(const float4*)(X + (size_t)(k0 + 8 + kl) * IPAD + Jb + i4);
        }
        #pragma unroll
        for (int kk = 0; kk < 8; kk++) {
            float a[8], b[8];
            *(float4*)&a[0] = *(const float4*)&As[kk][ty * 8];
            *(float4*)&a[4] = *(const float4*)&As[kk][ty * 8 + 4];
            *(float4*)&b[0] = *(const float4*)&Bs[kk][tx * 8];
            *(float4*)&b[4] = *(const float4*)&Bs[kk][tx * 8 + 4];
            #pragma unroll
            for (int u = 0; u < 8; u++)
                #pragma unroll
                for (int v = 0; v < 8; v++)
                    acc[u][v] = fmaf(a[u], b[v], acc[u][v]);
        }
        __syncthreads();
    }

    const int gib = Ib + ty * 8;
    const int gjb = Jb + tx * 8;
    #pragma unroll
    for (int u = 0; u < 8; u++) {
        int gi = gib + u;
        if (gi >= FF) continue;
        float si = g_sq[f * FF + gi];
        #pragma unroll
        for (int v = 0; v < 8; v++) {
            int gj = gjb + v;
            if (gj >= FF) continue;
            float sj = g_sq[f * FF + gj];
            float d = fmaxf(si + sj - 2.0f * acc[u][v], 0.0f);
            g_dist[((size_t)f * FF + gi) * FF + gj] = d;
            if (ti != tj)
                g_dist[((size_t)f * FF + gj) * FF + gi] = d;
        }
    }
}

// ---------------------------------------------------------------------------
// Top-8 smallest per row — warp per row, TWO-PASS sampled threshold (R11,
// rel_err 0.0; chunked: covers filters [fbase, fbase+2)). Dist slab is
// L2-resident when run right behind its gram chunk.
// ---------------------------------------------------------------------------
#define SENT_KEY 0x7F7FFFFFFFFFFFFFULL   // (FLT_MAX bits << 32) | 0xFFFFFFFF
#define FMAXV    3.402823466e+38f

__global__ void topk_kernel(int fbase) {
    const int wg   = (blockIdx.x * blockDim.x + threadIdx.x) >> 5;  // 0..2*FF-1
    const int lane = threadIdx.x & 31;
    if (wg >= 2 * FF) return;
    const int f = fbase + wg / FF;
    const int i = wg % FF;

    const float4* __restrict__ row4 =
        (const float4*)(g_dist + ((size_t)f * FF + i) * FF);

    // ---- Pass A: per-lane min (staged loads, MLP=4) ----
    float lmin = FMAXV;
    #pragma unroll
    for (int base = 0; base < 500; base += 128) {
        float4 d[4];
        #pragma unroll
        for (int t = 0; t < 4; t++) {
            int m = base + t * 32 + lane;
            d[t] = (m < 500) ? row4[m]
                             : make_float4(FMAXV, FMAXV, FMAXV, FMAXV);
        }
        #pragma unroll
        for (int t = 0; t < 4; t++)
            lmin = fminf(lmin, fminf(fminf(d[t].x, d[t].y),
                                     fminf(d[t].z, d[t].w)));
    }

    // T = 8th-smallest lane minimum (warp-min with retire; tie over-retire
    // only raises T — still a sound upper bound on the global 8th).
    float T;
    {
        float mv = lmin;
        #pragma unroll
        for (int r = 0; r < KNN; r++) {
            float m = mv;
            #pragma unroll
            for (int off = 16; off; off >>= 1)
                m = fminf(m, __shfl_xor_sync(0xffffffffu, m, off));
            T = m;
            if (mv == m) mv = FMAXV;   // retire winner(s)
        }
    }

    // ---- Pass B: exact insert of elements <= T (L1/L2-resident reload) ----
    unsigned long long k0 = SENT_KEY, k1 = SENT_KEY, k2 = SENT_KEY,
                       k3 = SENT_KEY, k4 = SENT_KEY, k5 = SENT_KEY,
                       k6 = SENT_KEY, k7 = SENT_KEY;

#define CSW(a, b) { if ((b) < (a)) { unsigned long long _t = (a); (a) = (b); (b) = _t; } }
#define TOPK_TRY(dv, jv)                                                      \
    if ((dv) <= T) {                                                          \
        unsigned long long key =                                              \
            ((unsigned long long)__float_as_uint(dv) << 32) | (unsigned)(jv); \
        if (key < k7) {                                                       \
            k7 = key;                                                         \
            CSW(k6, k7); CSW(k5, k6); CSW(k4, k5); CSW(k3, k4);               \
            CSW(k2, k3); CSW(k1, k2); CSW(k0, k1);                            \
        }                                                                     \
    }

    #pragma unroll
    for (int base = 0; base < 500; base += 128) {
        float4 d[4];
        int m4[4];
        #pragma unroll
        for (int t = 0; t < 4; t++) {
            m4[t] = base + t * 32 + lane;
            d[t] = (m4[t] < 500) ? row4[m4[t]]
                                 : make_float4(FMAXV, FMAXV, FMAXV, FMAXV);
        }
        #pragma unroll
        for (int t = 0; t < 4; t++) {
            float mn = fminf(fminf(d[t].x, d[t].y), fminf(d[t].z, d[t].w));
            if (mn <= T) {
                int j0 = m4[t] << 2;
                TOPK_TRY(d[t].x, j0 + 0);
                TOPK_TRY(d[t].y, j0 + 1);
                TOPK_TRY(d[t].z, j0 + 2);
                TOPK_TRY(d[t].w, j0 + 3);
            }
        }
    }
#undef TOPK_TRY
#undef CSW

    // Extraction: global min over lane heads; winner shifts its buffer.
    // All static indexing; keys unique (index embedded) -> single winner.
    #pragma unroll
    for (int r = 0; r < KNN; r++) {
        unsigned long long m = k0;
        #pragma unroll
        for (int off = 16; off; off >>= 1) {
            unsigned long long o = __shfl_xor_sync(0xffffffffu, m, off);
            m = (o < m) ? o : m;
        }
        if (k0 == m) {
            k0 = k1; k1 = k2; k2 = k3; k3 = k4;
            k4 = k5; k5 = k6; k6 = k7; k7 = 0xFFFFFFFFFFFFFFFFULL;
        }
        if (lane == 0)
            g_idx[(i * KNN + r) * NF + f] = (int)(m & 0xFFFFFFFFu);
    }
}

// ---------------------------------------------------------------------------
// out[b][i*8+k][c] = inputs[b][ idx[i][k][c] ][c]
// ---------------------------------------------------------------------------
__global__ void gather_kernel(const float* __restrict__ inputs,
                              float* __restrict__ out) {
    int g = blockIdx.x * blockDim.x + threadIdx.x;
    const int total = NB * FF * KNN * NF;
    if (g >= total) return;
    int c   = g & 15;
    int row = (g >> 4) % (FF * KNN);
    int b   = g / (FF * KNN * NF);
    int r   = g_idx[row * NF + c];
    out[g] = inputs[((size_t)b * FF + r) * NF + c];
}

// ---------------------------------------------------------------------------
// Launcher: pipelined fork/join. CAPTURE-LEGAL PROTOCOL (R12 bugfix): every
// side stream first waits on an event recorded on the origin stream (S0)
// BEFORE any launch on it — only then is its work capture-reachable.
//   S0:    [root] pack, gram chunks (even), gather
//   sGram: gram chunks (odd)
//   sTopk: sq, then topk chunk c after gram chunk c's event
// ---------------------------------------------------------------------------
extern "C" void kernel_launch(void* const* d_in, const int* in_sizes, int n_in,
                              void* d_out, int out_size) {
    const float* inputs = (const float*)d_in[0];   // (64, 2000, 16)
    const float* coords = (const float*)d_in[1];   // (512, 2000, 16)
    if (n_in >= 2 && in_sizes[0] == DC * FF * NF) {
        coords = (const float*)d_in[0];
        inputs = (const float*)d_in[1];
    }

    static cudaStream_t sGram = nullptr, sTopk = nullptr;
    static cudaEvent_t evRoot, evSq, evHead, evG[8], evT;
    static bool ready = false;
    if (!ready) {
        cudaStreamCreateWithFlags(&sGram, cudaStreamNonBlocking);
        cudaStreamCreateWithFlags(&sTopk, cudaStreamNonBlocking);
        cudaEventCreateWithFlags(&evRoot, cudaEventDisableTiming);
        cudaEventCreateWithFlags(&evSq,   cudaEventDisableTiming);
        cudaEventCreateWithFlags(&evHead, cudaEventDisableTiming);
        for (int c = 0; c < 8; c++)
            cudaEventCreateWithFlags(&evG[c], cudaEventDisableTiming);
        cudaEventCreateWithFlags(&evT, cudaEventDisableTiming);
        ready = true;
    }
    cudaStream_t S0 = 0;

    // Fork: make side streams capture-reachable BEFORE launching on them.
    cudaEventRecord(evRoot, S0);
    cudaStreamWaitEvent(sTopk, evRoot, 0);
    cudaStreamWaitEvent(sGram, evRoot, 0);

    // Head: pack on S0 || sq on sTopk; join into S0 (gram needs both).
    pack_kernel<<<dim3(32, DC), 256, 0, S0>>>(coords);
    sq_kernel<<<FF * NF / 32, 1024, 0, sTopk>>>(coords);
    cudaEventRecord(evSq, sTopk);
    cudaStreamWaitEvent(S0, evSq, 0);
    cudaEventRecord(evHead, S0);
    cudaStreamWaitEvent(sGram, evHead, 0);

    // Pipeline: 8 chunks x 2 filters. Gram alternates S0/sGram; each chunk's
    // event releases its topk on sTopk (dist slab L2-hot).
    for (int c = 0; c < 8; c++) {
        cudaStream_t Sg = (c & 1) ? sGram : S0;
        gram_kernel<<<dim3(136, 1, 2), 256, 0, Sg>>>(c * 2);
        cudaEventRecord(evG[c], Sg);
        cudaStreamWaitEvent(sTopk, evG[c], 0);
        topk_kernel<<<(2 * FF * 32) / 128, 128, 0, sTopk>>>(c * 2);
    }

    // Join: gather needs all g_idx; S0 must also see sGram's last chunk.
    cudaEventRecord(evT, sTopk);
    cudaStreamWaitEvent(S0, evT, 0);
    gather_kernel<<<(NB * FF * KNN * NF) / 256, 256, 0, S0>>>(inputs, (float*)d_out);
}